// round 14
// baseline (speedup 1.0000x reference)
// R14: variance-isolation round. Exact R5 champion GEMM configuration
// (4x gemm3_nt @ 81920B, 678us) with ONE safe edit: qe+qw splits merged.
#include <cuda_runtime.h>
#include <cuda_bf16.h>
#include <cstdint>
#include <math.h>

#define BB 16
#define RR 1024
#define TT 512
#define DD 1024

// ---------------------------------------------------------------------------
// Scratch (static device arrays — no runtime allocation allowed)
// ---------------------------------------------------------------------------
__device__ __align__(16) unsigned short g_Wrh[DD * DD], g_Wrl[DD * DD];
__device__ __align__(16) unsigned short g_Wqh[DD * DD], g_Wql[DD * DD];
__device__ __align__(16) unsigned short g_Mh[DD * DD],  g_Ml[DD * DD];
__device__ __align__(16) unsigned short g_rfh[BB * RR * DD], g_rfl[BB * RR * DD];
__device__ __align__(16) unsigned short g_qeh[BB * TT * DD], g_qel[BB * TT * DD];
__device__ __align__(16) unsigned short g_qwh[BB * TT * DD], g_qwl[BB * TT * DD];
__device__ __align__(16) unsigned short g_Nth[BB * TT * DD], g_Ntl[BB * TT * DD];
__device__ __align__(16) float g_S[BB * RR * TT];
__device__ __align__(16) float g_H[BB * RR * TT];
__device__ float g_w2[DD];
__device__ float g_c[BB * TT];
__device__ float g_e[BB * TT];
__device__ float g_f[BB * RR];

// ---------------------------------------------------------------------------
// MMA macro
// ---------------------------------------------------------------------------
#define MMA_BF16(c, a, b)                                                      \
    asm volatile(                                                              \
        "mma.sync.aligned.m16n8k16.row.col.f32.bf16.bf16.f32 "                 \
        "{%0,%1,%2,%3},{%4,%5,%6,%7},{%8,%9},{%0,%1,%2,%3};"                   \
        : "+f"(c[0]), "+f"(c[1]), "+f"(c[2]), "+f"(c[3])                       \
        : "r"(a[0]), "r"(a[1]), "r"(a[2]), "r"(a[3]), "r"(b[0]), "r"(b[1]))

// ---------------------------------------------------------------------------
// fp32 -> (bf16 hi, bf16 lo) split
// ---------------------------------------------------------------------------
__device__ __forceinline__ void sp(float v, unsigned short& h, unsigned short& l) {
    __nv_bfloat16 bh = __float2bfloat16_rn(v);
    float r = v - __bfloat162float(bh);
    __nv_bfloat16 bl = __float2bfloat16_rn(r);
    h = *reinterpret_cast<unsigned short*>(&bh);
    l = *reinterpret_cast<unsigned short*>(&bl);
}

__global__ void split_kernel(const float4* __restrict__ x,
                             ushort4* __restrict__ h, ushort4* __restrict__ l, int n4) {
    int i = blockIdx.x * blockDim.x + threadIdx.x;
    if (i >= n4) return;
    float4 v = x[i];
    ushort4 hh, ll;
    sp(v.x, hh.x, ll.x); sp(v.y, hh.y, ll.y);
    sp(v.z, hh.z, ll.z); sp(v.w, hh.w, ll.w);
    h[i] = hh; l[i] = ll;
}

// qe: bf16 split of qe AND of qe*Ws3 in one pass over qe
__global__ void split_qe_kernel(const float4* __restrict__ qe, const float* __restrict__ Ws3,
                                ushort4* __restrict__ h, ushort4* __restrict__ l,
                                ushort4* __restrict__ wh, ushort4* __restrict__ wl, int n4) {
    int i = blockIdx.x * blockDim.x + threadIdx.x;
    if (i >= n4) return;
    float4 v = qe[i];
    ushort4 hh, ll, whh, wll;
    sp(v.x, hh.x, ll.x); sp(v.y, hh.y, ll.y);
    sp(v.z, hh.z, ll.z); sp(v.w, hh.w, ll.w);
    int d0 = (i * 4) & (DD - 1);
    float4 w = *(const float4*)&Ws3[d0];
    sp(v.x * w.x, whh.x, wll.x); sp(v.y * w.y, whh.y, wll.y);
    sp(v.z * w.z, whh.z, wll.z); sp(v.w * w.w, whh.w, wll.w);
    h[i] = hh; l[i] = ll; wh[i] = whh; wl[i] = wll;
}

// ---------------------------------------------------------------------------
// PROVEN (R5, 678us) 3-pass split-bf16 NT GEMM on tensor cores.
//   C[M,N] = A[M,K] * B[N,K]^T  as Ah*Bh + Ah*Bl + Al*Bh (fp32 accum)
// CTA 128x128x32, 8 warps (warp 64x32), double-buffered smem (81920B).
// mode 0: fp32 C ; mode 1: split bf16 pair (Ch, Cl), batched stride sC.
// ---------------------------------------------------------------------------
__global__ __launch_bounds__(256, 1)
void gemm3_nt(const unsigned short* __restrict__ Ah, const unsigned short* __restrict__ Al,
              const unsigned short* __restrict__ Bh, const unsigned short* __restrict__ Bl,
              float* __restrict__ Cf, unsigned short* __restrict__ Ch,
              unsigned short* __restrict__ Cl,
              int Ndim, int K,
              long long sA, long long sB, long long sC, int mode) {
    extern __shared__ unsigned int smw[];
    const int tid = threadIdx.x, lane = tid & 31, warp = tid >> 5;
    const int g = lane >> 2, tq = lane & 3;
    const int wm = warp & 1, wn = warp >> 1;
    const int row0 = blockIdx.y * 128, col0 = blockIdx.x * 128;
    const long long z = blockIdx.z;

    const unsigned short* pAh = Ah + z * sA;
    const unsigned short* pAl = Al + z * sA;
    const unsigned short* pBh = Bh + z * sB;
    const unsigned short* pBl = Bl + z * sB;

    const int TW = 20, TSZ = 2560, BUF = 10240;

    float c[4][4][4];
    #pragma unroll
    for (int i = 0; i < 4; i++)
        #pragma unroll
        for (int j = 0; j < 4; j++)
            #pragma unroll
            for (int q = 0; q < 4; q++) c[i][j][q] = 0.f;

    uint4 st[8];

    auto LDG = [&](int k0) {
        #pragma unroll
        for (int t = 0; t < 2; t++) {
            int f = tid + t * 256; int r = f >> 2, q = f & 3;
            size_t oa = (size_t)(row0 + r) * K + k0 + q * 8;
            size_t ob = (size_t)(col0 + r) * K + k0 + q * 8;
            st[0 + t] = *(const uint4*)(pAh + oa);
            st[2 + t] = *(const uint4*)(pAl + oa);
            st[4 + t] = *(const uint4*)(pBh + ob);
            st[6 + t] = *(const uint4*)(pBl + ob);
        }
    };
    auto STS = [&](int buf) {
        unsigned base = buf * BUF;
        #pragma unroll
        for (int t = 0; t < 2; t++) {
            int f = tid + t * 256; int r = f >> 2, q = f & 3;
            unsigned o = r * TW + q * 4;
            *(uint4*)&smw[base + 0 * TSZ + o] = st[0 + t];
            *(uint4*)&smw[base + 1 * TSZ + o] = st[2 + t];
            *(uint4*)&smw[base + 2 * TSZ + o] = st[4 + t];
            *(uint4*)&smw[base + 3 * TSZ + o] = st[6 + t];
        }
    };

    LDG(0); STS(0); __syncthreads();

    const int steps = K >> 5;
    #pragma unroll 1
    for (int kt = 0; kt < steps; kt++) {
        int cur = kt & 1;
        if (kt + 1 < steps) LDG((kt + 1) << 5);
        unsigned base = cur * BUF;

        #pragma unroll
        for (int ks = 0; ks < 2; ks++) {
            unsigned ah[4][4], al[4][4], bh[4][2], bl[4][2];
            #pragma unroll
            for (int i = 0; i < 4; i++) {
                unsigned ro = (wm * 64 + i * 16 + g) * TW + ks * 8 + tq;
                ah[i][0] = smw[base + ro];
                ah[i][1] = smw[base + ro + 8 * TW];
                ah[i][2] = smw[base + ro + 4];
                ah[i][3] = smw[base + ro + 8 * TW + 4];
                al[i][0] = smw[base + TSZ + ro];
                al[i][1] = smw[base + TSZ + ro + 8 * TW];
                al[i][2] = smw[base + TSZ + ro + 4];
                al[i][3] = smw[base + TSZ + ro + 8 * TW + 4];
            }
            #pragma unroll
            for (int j = 0; j < 4; j++) {
                unsigned no = (wn * 32 + j * 8 + g) * TW + ks * 8 + tq;
                bh[j][0] = smw[base + 2 * TSZ + no];
                bh[j][1] = smw[base + 2 * TSZ + no + 4];
                bl[j][0] = smw[base + 3 * TSZ + no];
                bl[j][1] = smw[base + 3 * TSZ + no + 4];
            }
            #pragma unroll
            for (int i = 0; i < 4; i++)
                #pragma unroll
                for (int j = 0; j < 4; j++) {
                    MMA_BF16(c[i][j], ah[i], bh[j]);
                    MMA_BF16(c[i][j], ah[i], bl[j]);
                    MMA_BF16(c[i][j], al[i], bh[j]);
                }
        }
        if (kt + 1 < steps) STS(cur ^ 1);
        __syncthreads();
    }

    #pragma unroll
    for (int i = 0; i < 4; i++)
        #pragma unroll
        for (int j = 0; j < 4; j++) {
            int r  = row0 + wm * 64 + i * 16 + g;
            int cc = col0 + wn * 32 + j * 8 + tq * 2;
            if (mode == 0) {
                float* P = Cf + z * sC;
                *(float2*)&P[(size_t)r * Ndim + cc] = make_float2(c[i][j][0], c[i][j][1]);
                *(float2*)&P[(size_t)(r + 8) * Ndim + cc] = make_float2(c[i][j][2], c[i][j][3]);
            } else {
                unsigned short* PH = Ch + z * sC;
                unsigned short* PL = Cl + z * sC;
                unsigned short h0, l0, h1, l1;
                sp(c[i][j][0], h0, l0); sp(c[i][j][1], h1, l1);
                *(ushort2*)&PH[(size_t)r * Ndim + cc] = make_ushort2(h0, h1);
                *(ushort2*)&PL[(size_t)r * Ndim + cc] = make_ushort2(l0, l1);
                sp(c[i][j][2], h0, l0); sp(c[i][j][3], h1, l1);
                *(ushort2*)&PH[(size_t)(r + 8) * Ndim + cc] = make_ushort2(h0, h1);
                *(ushort2*)&PL[(size_t)(r + 8) * Ndim + cc] = make_ushort2(l0, l1);
            }
        }
}

// ---------------------------------------------------------------------------
// Small fp32 helper kernels
// ---------------------------------------------------------------------------
__global__ void w2_kernel(const float* __restrict__ Wq, const float* __restrict__ br,
                          float* __restrict__ w2) {
    int warp = (blockIdx.x * blockDim.x + threadIdx.x) >> 5;
    int lane = threadIdx.x & 31;
    if (warp >= DD) return;
    const float* row = Wq + (size_t)warp * DD;
    float s = 0.f;
    for (int h = lane; h < DD; h += 32) s += row[h] * br[h];
    #pragma unroll
    for (int o = 16; o; o >>= 1) s += __shfl_xor_sync(0xffffffffu, s, o);
    if (lane == 0) w2[warp] = s;
}

__global__ void ce_kernel(const float* __restrict__ qe, const float* __restrict__ w2,
                          const float* __restrict__ Ws2,
                          float* __restrict__ c, float* __restrict__ e) {
    int warp = (blockIdx.x * blockDim.x + threadIdx.x) >> 5;
    int lane = threadIdx.x & 31;
    if (warp >= BB * TT) return;
    const float* row = qe + (size_t)warp * DD;
    float sc = 0.f, se = 0.f;
    for (int d = lane; d < DD; d += 32) {
        float q = row[d];
        sc += q * w2[d];
        se += q * Ws2[d];
    }
    #pragma unroll
    for (int o = 16; o; o >>= 1) {
        sc += __shfl_xor_sync(0xffffffffu, sc, o);
        se += __shfl_xor_sync(0xffffffffu, se, o);
    }
    if (lane == 0) { c[warp] = sc; e[warp] = se; }
}

__global__ void f_kernel(const float* __restrict__ rf, const float* __restrict__ Ws1,
                         float* __restrict__ f) {
    int warp = (blockIdx.x * blockDim.x + threadIdx.x) >> 5;
    int lane = threadIdx.x & 31;
    if (warp >= BB * RR) return;
    const float* row = rf + (size_t)warp * DD;
    float s = 0.f;
    for (int d = lane; d < DD; d += 32) s += row[d] * Ws1[d];
    #pragma unroll
    for (int o = 16; o; o >>= 1) s += __shfl_xor_sync(0xffffffffu, s, o);
    if (lane == 0) f[warp] = s;
}

__global__ __launch_bounds__(256)
void finalize_kernel(const float* __restrict__ S, const float* __restrict__ Hm,
                     const float* __restrict__ c, const float* __restrict__ e,
                     const float* __restrict__ f, const float* __restrict__ bs,
                     float* __restrict__ out) {
    const int idx = blockIdx.x;
    const int b   = idx >> 10;
    const float* Srow = S  + (size_t)idx * TT;
    const float* Hrow = Hm + (size_t)idx * TT;
    const float* cb   = c + b * TT;
    const float* eb   = e + b * TT;
    const int tid = threadIdx.x;

    __shared__ float red[8];
    __shared__ float rs[8], ra[8];

    float m = -1e30f;
    for (int i = tid; i < TT; i += 256) m = fmaxf(m, Srow[i] + cb[i]);
    #pragma unroll
    for (int o = 16; o; o >>= 1) m = fmaxf(m, __shfl_xor_sync(0xffffffffu, m, o));
    if ((tid & 31) == 0) red[tid >> 5] = m;
    __syncthreads();
    if (tid < 8) {
        float v = red[tid];
        #pragma unroll
        for (int o = 4; o; o >>= 1) v = fmaxf(v, __shfl_xor_sync(0xffu, v, o));
        if (tid == 0) red[0] = v;
    }
    __syncthreads();
    m = red[0];

    float sum = 0.f, acc = 0.f;
    for (int i = tid; i < TT; i += 256) {
        float w = expf(Srow[i] + cb[i] - m);
        sum += w;
        acc += w * (eb[i] + Hrow[i]);
    }
    #pragma unroll
    for (int o = 16; o; o >>= 1) {
        sum += __shfl_xor_sync(0xffffffffu, sum, o);
        acc += __shfl_xor_sync(0xffffffffu, acc, o);
    }
    if ((tid & 31) == 0) { rs[tid >> 5] = sum; ra[tid >> 5] = acc; }
    __syncthreads();
    if (tid == 0) {
        float s = 0.f, a = 0.f;
        #pragma unroll
        for (int w = 0; w < 8; w++) { s += rs[w]; a += ra[w]; }
        out[idx] = a / s + f[idx] + bs[0];
    }
}

// ---------------------------------------------------------------------------
// Launch
// ---------------------------------------------------------------------------
extern "C" void kernel_launch(void* const* d_in, const int* in_sizes, int n_in,
                              void* d_out, int out_size) {
    const float* rf = (const float*)d_in[0];
    const float* qe = (const float*)d_in[1];
    const float* Wr = (const float*)d_in[2];
    const float* br = (const float*)d_in[3];
    const float* Wq = (const float*)d_in[4];
    // d_in[5] = bq: softmax-invariant, provably drops out
    const float* Ws = (const float*)d_in[6];
    const float* bs = (const float*)d_in[7];
    float* out = (float*)d_out;

    unsigned short *wrh, *wrl, *wqh, *wql, *mh, *ml, *rfh, *rfl, *qeh, *qel,
                   *qwh, *qwl, *nth, *ntl;
    float *gS, *gH, *gw2, *gc, *ge, *gf;
    cudaGetSymbolAddress((void**)&wrh, g_Wrh); cudaGetSymbolAddress((void**)&wrl, g_Wrl);
    cudaGetSymbolAddress((void**)&wqh, g_Wqh); cudaGetSymbolAddress((void**)&wql, g_Wql);
    cudaGetSymbolAddress((void**)&mh,  g_Mh);  cudaGetSymbolAddress((void**)&ml,  g_Ml);
    cudaGetSymbolAddress((void**)&rfh, g_rfh); cudaGetSymbolAddress((void**)&rfl, g_rfl);
    cudaGetSymbolAddress((void**)&qeh, g_qeh); cudaGetSymbolAddress((void**)&qel, g_qel);
    cudaGetSymbolAddress((void**)&qwh, g_qwh); cudaGetSymbolAddress((void**)&qwl, g_qwl);
    cudaGetSymbolAddress((void**)&nth, g_Nth); cudaGetSymbolAddress((void**)&ntl, g_Ntl);
    cudaGetSymbolAddress((void**)&gS,  g_S);   cudaGetSymbolAddress((void**)&gH,  g_H);
    cudaGetSymbolAddress((void**)&gw2, g_w2);  cudaGetSymbolAddress((void**)&gc,  g_c);
    cudaGetSymbolAddress((void**)&ge,  g_e);   cudaGetSymbolAddress((void**)&gf,  g_f);

    cudaFuncSetAttribute(gemm3_nt, cudaFuncAttributeMaxDynamicSharedMemorySize, 81920);

    // ---- splits ----
    {
        int n4 = DD * DD / 4;
        split_kernel<<<(n4 + 255) / 256, 256>>>((const float4*)Wr, (ushort4*)wrh, (ushort4*)wrl, n4);
        split_kernel<<<(n4 + 255) / 256, 256>>>((const float4*)Wq, (ushort4*)wqh, (ushort4*)wql, n4);
    }
    {
        int n4 = BB * RR * DD / 4;
        split_kernel<<<(n4 + 255) / 256, 256>>>((const float4*)rf, (ushort4*)rfh, (ushort4*)rfl, n4);
    }
    {
        int n4 = BB * TT * DD / 4;
        split_qe_kernel<<<(n4 + 255) / 256, 256>>>((const float4*)qe, Ws + 2 * DD,
                                                   (ushort4*)qeh, (ushort4*)qel,
                                                   (ushort4*)qwh, (ushort4*)qwl, n4);
    }

    // ---- small bias/vector terms (fp32) ----
    w2_kernel<<<(DD * 32 + 255) / 256, 256>>>(Wq, br, gw2);
    ce_kernel<<<(BB * TT * 32 + 255) / 256, 256>>>(qe, gw2, Ws + DD, gc, ge);
    f_kernel<<<(BB * RR * 32 + 255) / 256, 256>>>(rf, Ws, gf);

    // ---- M = Wr @ Wq^T -> split bf16 (mode 1) ----
    gemm3_nt<<<dim3(DD / 128, DD / 128, 1), 256, 81920>>>(
        wrh, wrl, wqh, wql, nullptr, mh, ml, DD, DD, 0, 0, 0, 1);

    // ---- Nt[b] = qe[b] @ M^T -> split bf16 [T,D] ----
    gemm3_nt<<<dim3(DD / 128, TT / 128, BB), 256, 81920>>>(
        qeh, qel, mh, ml, nullptr, nth, ntl, DD, DD,
        (long long)TT * DD, 0, (long long)TT * DD, 1);

    // ---- S[b] = rf[b] @ Nt[b]^T -> fp32 [R,T] ----
    gemm3_nt<<<dim3(TT / 128, RR / 128, BB), 256, 81920>>>(
        rfh, rfl, nth, ntl, gS, nullptr, nullptr, TT, DD,
        (long long)RR * DD, (long long)TT * DD, (long long)RR * TT, 0);

    // ---- H[b] = rf[b] @ qw[b]^T -> fp32 [R,T] ----
    gemm3_nt<<<dim3(TT / 128, RR / 128, BB), 256, 81920>>>(
        rfh, rfl, qwh, qwl, gH, nullptr, nullptr, TT, DD,
        (long long)RR * DD, (long long)TT * DD, (long long)RR * TT, 0);

    // ---- softmax + weighted reduce + bias terms ----
    finalize_kernel<<<BB * RR, 256>>>(gS, gH, gc, ge, gf, bs, out);
}

// round 15
// speedup vs baseline: 1.7537x; 1.7537x over previous
// R15: resubmission of the R13 minimum-work design (validated rel_err 1.7e-4).
// R14 proved cross-round timing variance of +52% on IDENTICAL code, so the
// optimization target is total work: S-path 3-pass bf16 (softmax-sensitive),
// H-term single-pass fp16 (post-softmax, linear). 126.6 GF vs 161 GF.
#include <cuda_runtime.h>
#include <cuda_bf16.h>
#include <cuda_fp16.h>
#include <cstdint>
#include <math.h>

#define BB 16
#define RR 1024
#define TT 512
#define DD 1024

// ---------------------------------------------------------------------------
// Scratch (static device arrays — no runtime allocation allowed)
// ---------------------------------------------------------------------------
__device__ __align__(16) unsigned short g_Wrh[DD * DD], g_Wrl[DD * DD];
__device__ __align__(16) unsigned short g_Wqh[DD * DD], g_Wql[DD * DD];
__device__ __align__(16) unsigned short g_Mh[DD * DD],  g_Ml[DD * DD];
__device__ __align__(16) unsigned short g_rfh[BB * RR * DD], g_rfl[BB * RR * DD];
__device__ __align__(16) unsigned short g_rfx[BB * RR * DD];   // fp16 rf
__device__ __align__(16) unsigned short g_qeh[BB * TT * DD], g_qel[BB * TT * DD];
__device__ __align__(16) unsigned short g_qwx[BB * TT * DD];   // fp16 qe*Ws3
__device__ __align__(16) unsigned short g_Nth[BB * TT * DD], g_Ntl[BB * TT * DD];
__device__ __align__(16) float g_S[BB * RR * TT];
__device__ __align__(16) float g_H[BB * RR * TT];
__device__ float g_w2[DD];
__device__ float g_c[BB * TT];
__device__ float g_e[BB * TT];
__device__ float g_f[BB * RR];

// ---------------------------------------------------------------------------
// MMA macros
// ---------------------------------------------------------------------------
#define MMA_BF16(c, a, b)                                                      \
    asm volatile(                                                              \
        "mma.sync.aligned.m16n8k16.row.col.f32.bf16.bf16.f32 "                 \
        "{%0,%1,%2,%3},{%4,%5,%6,%7},{%8,%9},{%0,%1,%2,%3};"                   \
        : "+f"(c[0]), "+f"(c[1]), "+f"(c[2]), "+f"(c[3])                       \
        : "r"(a[0]), "r"(a[1]), "r"(a[2]), "r"(a[3]), "r"(b[0]), "r"(b[1]))

#define MMA_F16(c, a, b)                                                       \
    asm volatile(                                                              \
        "mma.sync.aligned.m16n8k16.row.col.f32.f16.f16.f32 "                   \
        "{%0,%1,%2,%3},{%4,%5,%6,%7},{%8,%9},{%0,%1,%2,%3};"                   \
        : "+f"(c[0]), "+f"(c[1]), "+f"(c[2]), "+f"(c[3])                       \
        : "r"(a[0]), "r"(a[1]), "r"(a[2]), "r"(a[3]), "r"(b[0]), "r"(b[1]))

// ---------------------------------------------------------------------------
// fp32 -> (bf16 hi, bf16 lo) split ; fp32 -> fp16
// ---------------------------------------------------------------------------
__device__ __forceinline__ void sp(float v, unsigned short& h, unsigned short& l) {
    __nv_bfloat16 bh = __float2bfloat16_rn(v);
    float r = v - __bfloat162float(bh);
    __nv_bfloat16 bl = __float2bfloat16_rn(r);
    h = *reinterpret_cast<unsigned short*>(&bh);
    l = *reinterpret_cast<unsigned short*>(&bl);
}
__device__ __forceinline__ unsigned short f2h(float v) {
    __half hv = __float2half_rn(v);
    return *reinterpret_cast<unsigned short*>(&hv);
}

__global__ void split_kernel(const float4* __restrict__ x,
                             ushort4* __restrict__ h, ushort4* __restrict__ l, int n4) {
    int i = blockIdx.x * blockDim.x + threadIdx.x;
    if (i >= n4) return;
    float4 v = x[i];
    ushort4 hh, ll;
    sp(v.x, hh.x, ll.x); sp(v.y, hh.y, ll.y);
    sp(v.z, hh.z, ll.z); sp(v.w, hh.w, ll.w);
    h[i] = hh; l[i] = ll;
}

// rf: bf16 split + fp16 copy (one pass over rf)
__global__ void split_rf_kernel(const float4* __restrict__ x,
                                ushort4* __restrict__ h, ushort4* __restrict__ l,
                                ushort4* __restrict__ xf, int n4) {
    int i = blockIdx.x * blockDim.x + threadIdx.x;
    if (i >= n4) return;
    float4 v = x[i];
    ushort4 hh, ll, ff;
    sp(v.x, hh.x, ll.x); sp(v.y, hh.y, ll.y);
    sp(v.z, hh.z, ll.z); sp(v.w, hh.w, ll.w);
    ff.x = f2h(v.x); ff.y = f2h(v.y); ff.z = f2h(v.z); ff.w = f2h(v.w);
    h[i] = hh; l[i] = ll; xf[i] = ff;
}

// qe: bf16 split of qe + fp16 of qe*Ws3 (one pass over qe)
__global__ void split_qe_kernel(const float4* __restrict__ qe, const float* __restrict__ Ws3,
                                ushort4* __restrict__ h, ushort4* __restrict__ l,
                                ushort4* __restrict__ qw, int n4) {
    int i = blockIdx.x * blockDim.x + threadIdx.x;
    if (i >= n4) return;
    float4 v = qe[i];
    ushort4 hh, ll, ww;
    sp(v.x, hh.x, ll.x); sp(v.y, hh.y, ll.y);
    sp(v.z, hh.z, ll.z); sp(v.w, hh.w, ll.w);
    int d0 = (i * 4) & (DD - 1);
    float4 w = *(const float4*)&Ws3[d0];
    ww.x = f2h(v.x * w.x); ww.y = f2h(v.y * w.y);
    ww.z = f2h(v.z * w.z); ww.w = f2h(v.w * w.w);
    h[i] = hh; l[i] = ll; qw[i] = ww;
}

// ---------------------------------------------------------------------------
// PROVEN 3-pass split-bf16 NT GEMM on tensor cores.
//   C[M,N] = A[M,K] * B[N,K]^T  as Ah*Bh + Ah*Bl + Al*Bh (fp32 accum)
// CTA 128x128x32, 8 warps (warp 64x32), double-buffered smem (81920B).
// mode 0: fp32 C ; mode 1: split bf16 pair (Ch, Cl), batched stride sC.
// ---------------------------------------------------------------------------
__global__ __launch_bounds__(256, 1)
void gemm3_nt(const unsigned short* __restrict__ Ah, const unsigned short* __restrict__ Al,
              const unsigned short* __restrict__ Bh, const unsigned short* __restrict__ Bl,
              float* __restrict__ Cf, unsigned short* __restrict__ Ch,
              unsigned short* __restrict__ Cl,
              int Ndim, int K,
              long long sA, long long sB, long long sC, int mode) {
    extern __shared__ unsigned int smw[];
    const int tid = threadIdx.x, lane = tid & 31, warp = tid >> 5;
    const int g = lane >> 2, tq = lane & 3;
    const int wm = warp & 1, wn = warp >> 1;
    const int row0 = blockIdx.y * 128, col0 = blockIdx.x * 128;
    const long long z = blockIdx.z;

    const unsigned short* pAh = Ah + z * sA;
    const unsigned short* pAl = Al + z * sA;
    const unsigned short* pBh = Bh + z * sB;
    const unsigned short* pBl = Bl + z * sB;

    const int TW = 20, TSZ = 2560, BUF = 10240;

    float c[4][4][4];
    #pragma unroll
    for (int i = 0; i < 4; i++)
        #pragma unroll
        for (int j = 0; j < 4; j++)
            #pragma unroll
            for (int q = 0; q < 4; q++) c[i][j][q] = 0.f;

    uint4 st[8];

    auto LDG = [&](int k0) {
        #pragma unroll
        for (int t = 0; t < 2; t++) {
            int f = tid + t * 256; int r = f >> 2, q = f & 3;
            size_t oa = (size_t)(row0 + r) * K + k0 + q * 8;
            size_t ob = (size_t)(col0 + r) * K + k0 + q * 8;
            st[0 + t] = *(const uint4*)(pAh + oa);
            st[2 + t] = *(const uint4*)(pAl + oa);
            st[4 + t] = *(const uint4*)(pBh + ob);
            st[6 + t] = *(const uint4*)(pBl + ob);
        }
    };
    auto STS = [&](int buf) {
        unsigned base = buf * BUF;
        #pragma unroll
        for (int t = 0; t < 2; t++) {
            int f = tid + t * 256; int r = f >> 2, q = f & 3;
            unsigned o = r * TW + q * 4;
            *(uint4*)&smw[base + 0 * TSZ + o] = st[0 + t];
            *(uint4*)&smw[base + 1 * TSZ + o] = st[2 + t];
            *(uint4*)&smw[base + 2 * TSZ + o] = st[4 + t];
            *(uint4*)&smw[base + 3 * TSZ + o] = st[6 + t];
        }
    };

    LDG(0); STS(0); __syncthreads();

    const int steps = K >> 5;
    #pragma unroll 1
    for (int kt = 0; kt < steps; kt++) {
        int cur = kt & 1;
        if (kt + 1 < steps) LDG((kt + 1) << 5);
        unsigned base = cur * BUF;

        #pragma unroll
        for (int ks = 0; ks < 2; ks++) {
            unsigned ah[4][4], al[4][4], bh[4][2], bl[4][2];
            #pragma unroll
            for (int i = 0; i < 4; i++) {
                unsigned ro = (wm * 64 + i * 16 + g) * TW + ks * 8 + tq;
                ah[i][0] = smw[base + ro];
                ah[i][1] = smw[base + ro + 8 * TW];
                ah[i][2] = smw[base + ro + 4];
                ah[i][3] = smw[base + ro + 8 * TW + 4];
                al[i][0] = smw[base + TSZ + ro];
                al[i][1] = smw[base + TSZ + ro + 8 * TW];
                al[i][2] = smw[base + TSZ + ro + 4];
                al[i][3] = smw[base + TSZ + ro + 8 * TW + 4];
            }
            #pragma unroll
            for (int j = 0; j < 4; j++) {
                unsigned no = (wn * 32 + j * 8 + g) * TW + ks * 8 + tq;
                bh[j][0] = smw[base + 2 * TSZ + no];
                bh[j][1] = smw[base + 2 * TSZ + no + 4];
                bl[j][0] = smw[base + 3 * TSZ + no];
                bl[j][1] = smw[base + 3 * TSZ + no + 4];
            }
            #pragma unroll
            for (int i = 0; i < 4; i++)
                #pragma unroll
                for (int j = 0; j < 4; j++) {
                    MMA_BF16(c[i][j], ah[i], bh[j]);
                    MMA_BF16(c[i][j], ah[i], bl[j]);
                    MMA_BF16(c[i][j], al[i], bh[j]);
                }
        }
        if (kt + 1 < steps) STS(cur ^ 1);
        __syncthreads();
    }

    #pragma unroll
    for (int i = 0; i < 4; i++)
        #pragma unroll
        for (int j = 0; j < 4; j++) {
            int r  = row0 + wm * 64 + i * 16 + g;
            int cc = col0 + wn * 32 + j * 8 + tq * 2;
            if (mode == 0) {
                float* P = Cf + z * sC;
                *(float2*)&P[(size_t)r * Ndim + cc] = make_float2(c[i][j][0], c[i][j][1]);
                *(float2*)&P[(size_t)(r + 8) * Ndim + cc] = make_float2(c[i][j][2], c[i][j][3]);
            } else {
                unsigned short* PH = Ch + z * sC;
                unsigned short* PL = Cl + z * sC;
                unsigned short h0, l0, h1, l1;
                sp(c[i][j][0], h0, l0); sp(c[i][j][1], h1, l1);
                *(ushort2*)&PH[(size_t)r * Ndim + cc] = make_ushort2(h0, h1);
                *(ushort2*)&PL[(size_t)r * Ndim + cc] = make_ushort2(l0, l1);
                sp(c[i][j][2], h0, l0); sp(c[i][j][3], h1, l1);
                *(ushort2*)&PH[(size_t)(r + 8) * Ndim + cc] = make_ushort2(h0, h1);
                *(ushort2*)&PL[(size_t)(r + 8) * Ndim + cc] = make_ushort2(l0, l1);
            }
        }
}

// ---------------------------------------------------------------------------
// Single-pass fp16 NT GEMM (H term only — post-softmax, linear error path).
// Same proven layout, 1 operand per side, 40960B smem. fp32 output.
// ---------------------------------------------------------------------------
__global__ __launch_bounds__(256)
void gemm1_f16(const unsigned short* __restrict__ A, const unsigned short* __restrict__ B,
               float* __restrict__ Cf, int Ndim, int K,
               long long sA, long long sB, long long sC) {
    extern __shared__ unsigned int smw[];
    const int tid = threadIdx.x, lane = tid & 31, warp = tid >> 5;
    const int g = lane >> 2, tq = lane & 3;
    const int wm = warp & 1, wn = warp >> 1;
    const int row0 = blockIdx.y * 128, col0 = blockIdx.x * 128;
    const long long z = blockIdx.z;

    const unsigned short* pA = A + z * sA;
    const unsigned short* pB = B + z * sB;

    const int TW = 20, TSZ = 2560, BUF = 5120;

    float c[4][4][4];
    #pragma unroll
    for (int i = 0; i < 4; i++)
        #pragma unroll
        for (int j = 0; j < 4; j++)
            #pragma unroll
            for (int q = 0; q < 4; q++) c[i][j][q] = 0.f;

    uint4 st[4];

    auto LDG = [&](int k0) {
        #pragma unroll
        for (int t = 0; t < 2; t++) {
            int f = tid + t * 256; int r = f >> 2, q = f & 3;
            st[0 + t] = *(const uint4*)(pA + (size_t)(row0 + r) * K + k0 + q * 8);
            st[2 + t] = *(const uint4*)(pB + (size_t)(col0 + r) * K + k0 + q * 8);
        }
    };
    auto STS = [&](int buf) {
        unsigned base = buf * BUF;
        #pragma unroll
        for (int t = 0; t < 2; t++) {
            int f = tid + t * 256; int r = f >> 2, q = f & 3;
            unsigned o = r * TW + q * 4;
            *(uint4*)&smw[base + o] = st[0 + t];
            *(uint4*)&smw[base + TSZ + o] = st[2 + t];
        }
    };

    LDG(0); STS(0); __syncthreads();

    const int steps = K >> 5;
    #pragma unroll 1
    for (int kt = 0; kt < steps; kt++) {
        int cur = kt & 1;
        if (kt + 1 < steps) LDG((kt + 1) << 5);
        unsigned base = cur * BUF;

        #pragma unroll
        for (int ks = 0; ks < 2; ks++) {
            unsigned a4[4][4], b4[4][2];
            #pragma unroll
            for (int i = 0; i < 4; i++) {
                unsigned ro = (wm * 64 + i * 16 + g) * TW + ks * 8 + tq;
                a4[i][0] = smw[base + ro];
                a4[i][1] = smw[base + ro + 8 * TW];
                a4[i][2] = smw[base + ro + 4];
                a4[i][3] = smw[base + ro + 8 * TW + 4];
            }
            #pragma unroll
            for (int j = 0; j < 4; j++) {
                unsigned no = (wn * 32 + j * 8 + g) * TW + ks * 8 + tq;
                b4[j][0] = smw[base + TSZ + no];
                b4[j][1] = smw[base + TSZ + no + 4];
            }
            #pragma unroll
            for (int i = 0; i < 4; i++)
                #pragma unroll
                for (int j = 0; j < 4; j++)
                    MMA_F16(c[i][j], a4[i], b4[j]);
        }
        if (kt + 1 < steps) STS(cur ^ 1);
        __syncthreads();
    }

    #pragma unroll
    for (int i = 0; i < 4; i++)
        #pragma unroll
        for (int j = 0; j < 4; j++) {
            int r  = row0 + wm * 64 + i * 16 + g;
            int cc = col0 + wn * 32 + j * 8 + tq * 2;
            float* P = Cf + z * sC;
            *(float2*)&P[(size_t)r * Ndim + cc] = make_float2(c[i][j][0], c[i][j][1]);
            *(float2*)&P[(size_t)(r + 8) * Ndim + cc] = make_float2(c[i][j][2], c[i][j][3]);
        }
}

// ---------------------------------------------------------------------------
// Small fp32 helper kernels
// ---------------------------------------------------------------------------
__global__ void w2_kernel(const float* __restrict__ Wq, const float* __restrict__ br,
                          float* __restrict__ w2) {
    int warp = (blockIdx.x * blockDim.x + threadIdx.x) >> 5;
    int lane = threadIdx.x & 31;
    if (warp >= DD) return;
    const float* row = Wq + (size_t)warp * DD;
    float s = 0.f;
    for (int h = lane; h < DD; h += 32) s += row[h] * br[h];
    #pragma unroll
    for (int o = 16; o; o >>= 1) s += __shfl_xor_sync(0xffffffffu, s, o);
    if (lane == 0) w2[warp] = s;
}

__global__ void ce_kernel(const float* __restrict__ qe, const float* __restrict__ w2,
                          const float* __restrict__ Ws2,
                          float* __restrict__ c, float* __restrict__ e) {
    int warp = (blockIdx.x * blockDim.x + threadIdx.x) >> 5;
    int lane = threadIdx.x & 31;
    if (warp >= BB * TT) return;
    const float* row = qe + (size_t)warp * DD;
    float sc = 0.f, se = 0.f;
    for (int d = lane; d < DD; d += 32) {
        float q = row[d];
        sc += q * w2[d];
        se += q * Ws2[d];
    }
    #pragma unroll
    for (int o = 16; o; o >>= 1) {
        sc += __shfl_xor_sync(0xffffffffu, sc, o);
        se += __shfl_xor_sync(0xffffffffu, se, o);
    }
    if (lane == 0) { c[warp] = sc; e[warp] = se; }
}

__global__ void f_kernel(const float* __restrict__ rf, const float* __restrict__ Ws1,
                         float* __restrict__ f) {
    int warp = (blockIdx.x * blockDim.x + threadIdx.x) >> 5;
    int lane = threadIdx.x & 31;
    if (warp >= BB * RR) return;
    const float* row = rf + (size_t)warp * DD;
    float s = 0.f;
    for (int d = lane; d < DD; d += 32) s += row[d] * Ws1[d];
    #pragma unroll
    for (int o = 16; o; o >>= 1) s += __shfl_xor_sync(0xffffffffu, s, o);
    if (lane == 0) f[warp] = s;
}

__global__ __launch_bounds__(256)
void finalize_kernel(const float* __restrict__ S, const float* __restrict__ Hm,
                     const float* __restrict__ c, const float* __restrict__ e,
                     const float* __restrict__ f, const float* __restrict__ bs,
                     float* __restrict__ out) {
    const int idx = blockIdx.x;
    const int b   = idx >> 10;
    const float* Srow = S  + (size_t)idx * TT;
    const float* Hrow = Hm + (size_t)idx * TT;
    const float* cb   = c + b * TT;
    const float* eb   = e + b * TT;
    const int tid = threadIdx.x;

    __shared__ float red[8];
    __shared__ float rs[8], ra[8];

    float m = -1e30f;
    for (int i = tid; i < TT; i += 256) m = fmaxf(m, Srow[i] + cb[i]);
    #pragma unroll
    for (int o = 16; o; o >>= 1) m = fmaxf(m, __shfl_xor_sync(0xffffffffu, m, o));
    if ((tid & 31) == 0) red[tid >> 5] = m;
    __syncthreads();
    if (tid < 8) {
        float v = red[tid];
        #pragma unroll
        for (int o = 4; o; o >>= 1) v = fmaxf(v, __shfl_xor_sync(0xffu, v, o));
        if (tid == 0) red[0] = v;
    }
    __syncthreads();
    m = red[0];

    float sum = 0.f, acc = 0.f;
    for (int i = tid; i < TT; i += 256) {
        float w = expf(Srow[i] + cb[i] - m);
        sum += w;
        acc += w * (eb[i] + Hrow[i]);
    }
    #pragma unroll
    for (int o = 16; o; o >>= 1) {
        sum += __shfl_xor_sync(0xffffffffu, sum, o);
        acc += __shfl_xor_sync(0xffffffffu, acc, o);
    }
    if ((tid & 31) == 0) { rs[tid >> 5] = sum; ra[tid >> 5] = acc; }
    __syncthreads();
    if (tid == 0) {
        float s = 0.f, a = 0.f;
        #pragma unroll
        for (int w = 0; w < 8; w++) { s += rs[w]; a += ra[w]; }
        out[idx] = a / s + f[idx] + bs[0];
    }
}

// ---------------------------------------------------------------------------
// Launch
// ---------------------------------------------------------------------------
extern "C" void kernel_launch(void* const* d_in, const int* in_sizes, int n_in,
                              void* d_out, int out_size) {
    const float* rf = (const float*)d_in[0];
    const float* qe = (const float*)d_in[1];
    const float* Wr = (const float*)d_in[2];
    const float* br = (const float*)d_in[3];
    const float* Wq = (const float*)d_in[4];
    // d_in[5] = bq: softmax-invariant, provably drops out
    const float* Ws = (const float*)d_in[6];
    const float* bs = (const float*)d_in[7];
    float* out = (float*)d_out;

    unsigned short *wrh, *wrl, *wqh, *wql, *mh, *ml, *rfh, *rfl, *rfx,
                   *qeh, *qel, *qwx, *nth, *ntl;
    float *gS, *gH, *gw2, *gc, *ge, *gf;
    cudaGetSymbolAddress((void**)&wrh, g_Wrh); cudaGetSymbolAddress((void**)&wrl, g_Wrl);
    cudaGetSymbolAddress((void**)&wqh, g_Wqh); cudaGetSymbolAddress((void**)&wql, g_Wql);
    cudaGetSymbolAddress((void**)&mh,  g_Mh);  cudaGetSymbolAddress((void**)&ml,  g_Ml);
    cudaGetSymbolAddress((void**)&rfh, g_rfh); cudaGetSymbolAddress((void**)&rfl, g_rfl);
    cudaGetSymbolAddress((void**)&rfx, g_rfx);
    cudaGetSymbolAddress((void**)&qeh, g_qeh); cudaGetSymbolAddress((void**)&qel, g_qel);
    cudaGetSymbolAddress((void**)&qwx, g_qwx);
    cudaGetSymbolAddress((void**)&nth, g_Nth); cudaGetSymbolAddress((void**)&ntl, g_Ntl);
    cudaGetSymbolAddress((void**)&gS,  g_S);   cudaGetSymbolAddress((void**)&gH,  g_H);
    cudaGetSymbolAddress((void**)&gw2, g_w2);  cudaGetSymbolAddress((void**)&gc,  g_c);
    cudaGetSymbolAddress((void**)&ge,  g_e);   cudaGetSymbolAddress((void**)&gf,  g_f);

    cudaFuncSetAttribute(gemm3_nt, cudaFuncAttributeMaxDynamicSharedMemorySize, 81920);
    cudaFuncSetAttribute(gemm1_f16, cudaFuncAttributeMaxDynamicSharedMemorySize, 40960);

    // ---- splits ----
    {
        int n4 = DD * DD / 4;
        split_kernel<<<(n4 + 255) / 256, 256>>>((const float4*)Wr, (ushort4*)wrh, (ushort4*)wrl, n4);
        split_kernel<<<(n4 + 255) / 256, 256>>>((const float4*)Wq, (ushort4*)wqh, (ushort4*)wql, n4);
    }
    {
        int n4 = BB * RR * DD / 4;
        split_rf_kernel<<<(n4 + 255) / 256, 256>>>((const float4*)rf, (ushort4*)rfh,
                                                   (ushort4*)rfl, (ushort4*)rfx, n4);
    }
    {
        int n4 = BB * TT * DD / 4;
        split_qe_kernel<<<(n4 + 255) / 256, 256>>>((const float4*)qe, Ws + 2 * DD,
                                                   (ushort4*)qeh, (ushort4*)qel,
                                                   (ushort4*)qwx, n4);
    }

    // ---- small bias/vector terms (fp32) ----
    w2_kernel<<<(DD * 32 + 255) / 256, 256>>>(Wq, br, gw2);
    ce_kernel<<<(BB * TT * 32 + 255) / 256, 256>>>(qe, gw2, Ws + DD, gc, ge);
    f_kernel<<<(BB * RR * 32 + 255) / 256, 256>>>(rf, Ws, gf);

    // ---- M = Wr @ Wq^T -> split bf16 (mode 1) ----
    gemm3_nt<<<dim3(DD / 128, DD / 128, 1), 256, 81920>>>(
        wrh, wrl, wqh, wql, nullptr, mh, ml, DD, DD, 0, 0, 0, 1);

    // ---- Nt[b] = qe[b] @ M^T -> split bf16 [T,D] ----
    gemm3_nt<<<dim3(DD / 128, TT / 128, BB), 256, 81920>>>(
        qeh, qel, mh, ml, nullptr, nth, ntl, DD, DD,
        (long long)TT * DD, 0, (long long)TT * DD, 1);

    // ---- S[b] = rf[b] @ Nt[b]^T -> fp32 [R,T] (3-pass bf16) ----
    gemm3_nt<<<dim3(TT / 128, RR / 128, BB), 256, 81920>>>(
        rfh, rfl, nth, ntl, gS, nullptr, nullptr, TT, DD,
        (long long)RR * DD, (long long)TT * DD, (long long)RR * TT, 0);

    // ---- H[b] = rf[b] @ qw[b]^T -> fp32 [R,T] (single-pass fp16) ----
    gemm1_f16<<<dim3(TT / 128, RR / 128, BB), 256, 40960>>>(
        rfx, qwx, gH, TT, DD,
        (long long)RR * DD, (long long)TT * DD, (long long)RR * TT);

    // ---- softmax + weighted reduce + bias terms ----
    finalize_kernel<<<BB * RR, 256>>>(gS, gH, gc, ge, gf, bs, out);
}